// round 17
// baseline (speedup 1.0000x reference)
#include <cuda_runtime.h>
#include <stdint.h>

#define NU 8000
#define NI 4000
#define NN 12000
#define NE 300000
#define ED 64
#define PAD 128                    // padded row capacity (max deg ~90 @ mean 50)

// ---- static device scratch (no allocations allowed) ----
__device__ int   g_deg[NN];              // append cursor -> dedup'd row length
__device__ float g_dsqrtinv[NN];
__device__ int   g_colpad[NN * PAD];     // 6.1 MB padded adjacency
__device__ float g_bufA[NN * ED];        // scaled embeddings y = dsinv * x
__device__ float g_bufB[NN * ED];
__device__ int   g_is64;                 // 1 if edge_index is int64

// ---------------- prep: clear deg + detect edge_index dtype ----------------
__global__ void lg_prep_kernel(const unsigned int* __restrict__ ei_raw) {
    int idx = blockIdx.x * blockDim.x + threadIdx.x;
    int stride = gridDim.x * blockDim.x;
    for (int w = idx; w < NN; w += stride) g_deg[w] = 0;
    if (blockIdx.x == 0 && threadIdx.x == 0) {
        // int64 little-endian values < 12000 => every odd 32-bit word is 0.
        int all_zero = 1;
        for (int k = 0; k < 128; ++k) {
            if (ei_raw[2 * k + 1] != 0u) { all_zero = 0; break; }
        }
        g_is64 = all_zero;
    }
}

// ---------------- append both directions (duplicates allowed) ----------------
__global__ void lg_mark_kernel(const int* __restrict__ ei) {
    int e = blockIdx.x * blockDim.x + threadIdx.x;
    if (e >= NE) return;
    int u, v;
    if (g_is64) {
        u = ei[2 * e];
        v = ei[2 * (NE + e)];
    } else {
        u = ei[e];
        v = ei[NE + e];
    }
    int s0 = atomicAdd(&g_deg[u], 1);
    if (s0 < PAD) g_colpad[u * PAD + s0] = v;
    int s1 = atomicAdd(&g_deg[v], 1);
    if (s1 < PAD) g_colpad[v * PAD + s1] = u;
}

// ---------------- dedup rows (warp per row) + fused rsqrt ----------------
__global__ void __launch_bounds__(256) lg_dedup_kernel() {
    __shared__ int sm[8][PAD];
    int w = threadIdx.x >> 5;
    int lane = threadIdx.x & 31;
    int row = blockIdx.x * 8 + w;
    if (row >= NN) return;
    int L = g_deg[row];
    if (L > PAD) L = PAD;
    int* cols = g_colpad + row * PAD;
    for (int p = lane; p < L; p += 32) sm[w][p] = cols[p];
    __syncwarp();
    int outpos = 0;
    for (int base = 0; base < L; base += 32) {
        int p = base + lane;
        bool valid = p < L;
        int c = valid ? sm[w][p] : -1;
        bool keep = valid;
        if (valid) {
            for (int q = 0; q < p; ++q) {
                if (sm[w][q] == c) { keep = false; break; }
            }
        }
        unsigned int m = __ballot_sync(0xffffffffu, keep);
        if (keep) {
            int off = __popc(m & ((1u << lane) - 1));
            cols[outpos + off] = c;       // writes to global copy; sm untouched
        }
        outpos += __popc(m);
    }
    if (lane == 0) {
        g_deg[row] = outpos;
        g_dsqrtinv[row] = rsqrtf((float)(outpos > 1 ? outpos : 1));
    }
}

// ---------------- init: accum = x0, bufA = dsinv * x0 ----------------
__global__ void lg_init_kernel(const float* __restrict__ uemb,
                               const float* __restrict__ iemb,
                               float* __restrict__ out) {
    int idx = blockIdx.x * blockDim.x + threadIdx.x;
    if (idx >= NN * ED) return;
    float v;
    if (idx < NU * ED) v = uemb[idx];
    else               v = iemb[idx - NU * ED];
    out[idx] = v;
    g_bufA[idx] = v * g_dsqrtinv[idx / ED];
}

// ---------------- SpMM over padded rows, pre-scaled gathers ----------------
// out_i = dsinv_i * sum_j y_j ;  ynext_i = dsinv_i * out_i ; accum=(accum+out)*scale
// flip=0: read bufA write bufB; flip=1: read bufB write bufA.
// Device-symbol pointers resolved in device code (host-side &g_bufX would be
// the host shadow; GB300 ATS makes that silently readable => zeros).
__global__ void __launch_bounds__(64) lg_spmm_kernel(int flip,
                                                     float* __restrict__ accum,
                                                     float scale) {
    const float* __restrict__ yin = flip ? g_bufB : g_bufA;
    float* __restrict__ yout      = flip ? g_bufA : g_bufB;
    __shared__ float4 sh[16];
    int i = blockIdx.x;
    int t = threadIdx.x;
    int lane16 = t & 15;          // dim group: dims [lane16*4, lane16*4+4)
    int slot   = t >> 4;          // neighbor slot 0..3
    int L = g_deg[i];
    const int* __restrict__ cols = g_colpad + i * PAD;
    float4 acc = make_float4(0.f, 0.f, 0.f, 0.f);

    int p = slot;
    for (; p + 4 < L; p += 8) {
        int c0 = cols[p];
        int c1 = cols[p + 4];
        float4 x0 = *(const float4*)(yin + (size_t)c0 * ED + lane16 * 4);
        float4 x1 = *(const float4*)(yin + (size_t)c1 * ED + lane16 * 4);
        acc.x += x0.x + x1.x;
        acc.y += x0.y + x1.y;
        acc.z += x0.z + x1.z;
        acc.w += x0.w + x1.w;
    }
    if (p < L) {
        int c = cols[p];
        float4 xv = *(const float4*)(yin + (size_t)c * ED + lane16 * 4);
        acc.x += xv.x; acc.y += xv.y; acc.z += xv.z; acc.w += xv.w;
    }

    // combine slot pairs within each warp (lanes t and t+16)
    acc.x += __shfl_down_sync(0xffffffffu, acc.x, 16);
    acc.y += __shfl_down_sync(0xffffffffu, acc.y, 16);
    acc.z += __shfl_down_sync(0xffffffffu, acc.z, 16);
    acc.w += __shfl_down_sync(0xffffffffu, acc.w, 16);
    if (t >= 32 && t < 48) sh[lane16] = acc;     // slots 2+3 partial
    __syncthreads();
    if (t < 16) {
        float di = g_dsqrtinv[i];
        float4 o = sh[lane16];
        float ox = di * (acc.x + o.x);
        float oy = di * (acc.y + o.y);
        float oz = di * (acc.z + o.z);
        float ow = di * (acc.w + o.w);
        size_t off = (size_t)i * ED + lane16 * 4;
        float4 y;
        y.x = di * ox; y.y = di * oy; y.z = di * oz; y.w = di * ow;
        *(float4*)(yout + off) = y;
        float4 a = *(float4*)(accum + off);
        a.x = (a.x + ox) * scale;
        a.y = (a.y + oy) * scale;
        a.z = (a.z + oz) * scale;
        a.w = (a.w + ow) * scale;
        *(float4*)(accum + off) = a;
    }
}

extern "C" void kernel_launch(void* const* d_in, const int* in_sizes, int n_in,
                              void* d_out, int out_size) {
    const int*   edge_index = (const int*)d_in[0];   // (2, NE) int32 (or int64; detected)
    const float* user_emb   = (const float*)d_in[1]; // (NU, 64)
    const float* item_emb   = (const float*)d_in[2]; // (NI, 64)
    float* out = (float*)d_out;                       // (NN, 64) concat(users, items)

    (void)in_sizes; (void)n_in; (void)out_size;

    // 1. clear deg + detect dtype (one launch)
    lg_prep_kernel<<<32, 384>>>((const unsigned int*)d_in[0]);
    // 2. append both directions into padded adjacency (dups allowed)
    lg_mark_kernel<<<(NE + 127) / 128, 128>>>(edge_index);
    // 3. dedup rows in-place + dsqrtinv = rsqrt(max(deg,1))
    lg_dedup_kernel<<<(NN + 7) / 8, 256>>>();
    // 4. accum = x0; bufA = dsinv * x0
    lg_init_kernel<<<(NN * ED + 255) / 256, 256>>>(user_emb, item_emb, out);
    // 5. three propagation layers; accumulate; mean(4 layers) on the last
    lg_spmm_kernel<<<NN, 64>>>(0, out, 1.0f);
    lg_spmm_kernel<<<NN, 64>>>(1, out, 1.0f);
    lg_spmm_kernel<<<NN, 64>>>(0, out, 0.25f);
}